// round 5
// baseline (speedup 1.0000x reference)
#include <cuda_runtime.h>
#include <math.h>

#define NB   8
#define NT   500
#define NF   257
#define NC   8
#define NNUL 4
#define LOWF 5
#define HIGHF 70
#define NBAND (HIGHF-LOWF)          // 65
#define DCF_SIZE (NB*NT*NF*NNUL)

#define OMA   0.65f
#define AOVER 0.53846156f           // a/(1-a)

// ---------------- scratch ----------------
__device__ float g_pre[NB*NT];
__device__ float g_aft[NB*NT*NNUL];

// ---------------- decayed Kogge-Stone over 32 lanes --------------------------
__device__ __forceinline__ void scan9(float u[9], int lane) {
    const float AJ0=0.35f, AJ1=0.1225f, AJ2=0.01500625f,
                AJ3=2.25187539e-4f, AJ4=5.07094278e-8f;
    #pragma unroll
    for (int kk = 0; kk < 9; kk++) {
        float v;
        v = __shfl_up_sync(0xffffffffu, u[kk], 1);  if (lane>=1)  u[kk]=fmaf(AJ0,v,u[kk]);
        v = __shfl_up_sync(0xffffffffu, u[kk], 2);  if (lane>=2)  u[kk]=fmaf(AJ1,v,u[kk]);
        v = __shfl_up_sync(0xffffffffu, u[kk], 4);  if (lane>=4)  u[kk]=fmaf(AJ2,v,u[kk]);
        v = __shfl_up_sync(0xffffffffu, u[kk], 8);  if (lane>=8)  u[kk]=fmaf(AJ3,v,u[kk]);
        v = __shfl_up_sync(0xffffffffu, u[kk], 16); if (lane>=16) u[kk]=fmaf(AJ4,v,u[kk]);
    }
}

// ---------------- weights -> registers ---------------------------------------
__device__ __forceinline__ void load_w_regs(const float* __restrict__ tw,
                                            const float* __restrict__ nw,
                                            int beam, int f,
                                            float twr[8], float twi[8],
                                            float nwr[NNUL][8], float nwi[NNUL][8]) {
    const float* twrp = tw + ((beam*2 + 0)*NF + f)*NC;
    const float* twip = tw + ((beam*2 + 1)*NF + f)*NC;
    float4 a0 = ((const float4*)twrp)[0], a1 = ((const float4*)twrp)[1];
    float4 b0 = ((const float4*)twip)[0], b1 = ((const float4*)twip)[1];
    twr[0]=a0.x; twr[1]=a0.y; twr[2]=a0.z; twr[3]=a0.w;
    twr[4]=a1.x; twr[5]=a1.y; twr[6]=a1.z; twr[7]=a1.w;
    twi[0]=b0.x; twi[1]=b0.y; twi[2]=b0.z; twi[3]=b0.w;
    twi[4]=b1.x; twi[5]=b1.y; twi[6]=b1.z; twi[7]=b1.w;
    #pragma unroll
    for (int n = 0; n < NNUL; n++) {
        const float* nrp = nw + (((beam*NNUL + n)*2 + 0)*NF + f)*NC;
        const float* nip = nw + (((beam*NNUL + n)*2 + 1)*NF + f)*NC;
        float4 c0 = ((const float4*)nrp)[0], c1 = ((const float4*)nrp)[1];
        float4 d0 = ((const float4*)nip)[0], d1 = ((const float4*)nip)[1];
        nwr[n][0]=c0.x; nwr[n][1]=c0.y; nwr[n][2]=c0.z; nwr[n][3]=c0.w;
        nwr[n][4]=c1.x; nwr[n][5]=c1.y; nwr[n][6]=c1.z; nwr[n][7]=c1.w;
        nwi[n][0]=d0.x; nwi[n][1]=d0.y; nwi[n][2]=d0.z; nwi[n][3]=d0.w;
        nwi[n][4]=d1.x; nwi[n][5]=d1.y; nwi[n][6]=d1.z; nwi[n][7]=d1.w;
    }
}

// ---------------- one (b,f,t) point -> u[9] (premultiplied by 1-a) ----------
__device__ __forceinline__ void point_u(const float* __restrict__ in,
                                        const float twr[8], const float twi[8],
                                        const float nwr[NNUL][8], const float nwi[NNUL][8],
                                        int b, int f, int t,
                                        float u[9], float& trO, float& tiO) {
    const float* xrp = in + ((size_t)(b*NT + t)*2 + 0)*(NF*NC) + f*NC;
    const float* xip = in + ((size_t)(b*NT + t)*2 + 1)*(NF*NC) + f*NC;
    float xr[8], xi[8];
    {
        float4 v0 = ((const float4*)xrp)[0], v1 = ((const float4*)xrp)[1];
        float4 w0 = ((const float4*)xip)[0], w1 = ((const float4*)xip)[1];
        xr[0]=v0.x; xr[1]=v0.y; xr[2]=v0.z; xr[3]=v0.w;
        xr[4]=v1.x; xr[5]=v1.y; xr[6]=v1.z; xr[7]=v1.w;
        xi[0]=w0.x; xi[1]=w0.y; xi[2]=w0.z; xi[3]=w0.w;
        xi[4]=w1.x; xi[5]=w1.y; xi[6]=w1.z; xi[7]=w1.w;
    }
    float tr=0.f, ti=0.f, pw=0.f;
    #pragma unroll
    for (int c = 0; c < 8; c++) {
        tr = fmaf(twr[c], xr[c], tr); tr = fmaf(-twi[c], xi[c], tr);
        ti = fmaf(twi[c], xr[c], ti); ti = fmaf( twr[c], xi[c], ti);
        pw = fmaf(xr[c], xr[c], pw);  pw = fmaf(xi[c], xi[c], pw);
    }
    pw *= 0.125f;
    trO = tr; tiO = ti;

    #pragma unroll
    for (int n = 0; n < NNUL; n++) {
        float nr=0.f, ni=0.f;
        #pragma unroll
        for (int c = 0; c < 8; c++) {
            nr = fmaf(nwr[n][c], xr[c], nr); nr = fmaf(-nwi[n][c], xi[c], nr);
            ni = fmaf(nwi[n][c], xr[c], ni); ni = fmaf( nwr[n][c], xi[c], ni);
        }
        float pr = tr*nr + ti*ni;
        float pi = ti*nr - tr*ni;
        if (t == 0) {   // reference's t=0 quirk (only iteration 0, lane 0)
            pr = fmaf( AOVER*ti, ni, pr);
            pi = fmaf(-AOVER*tr, ni, pi);
        }
        u[n]   = OMA*pr;
        u[4+n] = OMA*pi;
    }
    u[8] = OMA*pw;
}

// =================== K0: zero band accumulators ==============================
__global__ void k0_zero(void) {
    int i = blockIdx.x*256 + threadIdx.x;
    if (i < NB*NT)      g_pre[i] = 0.0f;
    if (i < NB*NT*NNUL) g_aft[i] = 0.0f;
}

// =================== K2a: band sums, 1 warp per f, full serial scan =========
#define BGRP 17   // ceil(65/4)
__global__ __launch_bounds__(128)
void k2a_band(const float* __restrict__ in, const int* __restrict__ beam_id,
              const float* __restrict__ tw, const float* __restrict__ nw) {
    int tid = threadIdx.x, lane = tid & 31, w = tid >> 5;
    int fg = blockIdx.x % BGRP;
    int b  = blockIdx.x / BGRP;
    int fo = fg*4 + w;                 // 0..67
    bool fv = fo < NBAND;
    int f  = LOWF + min(fo, NBAND-1);
    int beam = beam_id[b];

    float twr[8], twi[8], nwr[NNUL][8], nwi[NNUL][8];
    load_w_regs(tw, nw, beam, f, twr, twi, nwr, nwi);

    float pa = exp2f((float)(lane+1) * -1.5145732f);
    float carry[9];
    #pragma unroll
    for (int k = 0; k < 9; k++) carry[k] = 0.0f;

    for (int it = 0; it < 16; it++) {
        int t  = it*32 + lane;
        int tc = min(t, NT-1);
        float u[9], tr, ti;
        point_u(in, twr, twi, nwr, nwi, b, f, tc, u, tr, ti);
        scan9(u, lane);
        float y[9];
        #pragma unroll
        for (int k = 0; k < 9; k++) y[k] = fmaf(pa, carry[k], u[k]);
        #pragma unroll
        for (int k = 0; k < 9; k++) carry[k] = __shfl_sync(0xffffffffu, y[k], 31);

        if (fv && t < NT) {
            atomicAdd(g_pre + b*NT + t, y[8]);
            float* aftp = g_aft + (b*NT + t)*NNUL;
            #pragma unroll
            for (int n = 0; n < NNUL; n++)
                atomicAdd(aftp + n, sqrtf(fmaf(y[n], y[n], y[4+n]*y[4+n])));
        }
    }
}

// =================== K1: fused beamform+scan+ratio -> final dcf + targ ======
#define FGRP 65   // ceil(257/4)
__global__ __launch_bounds__(128)
void k1_fused(const float* __restrict__ in, const int* __restrict__ beam_id,
              const float* __restrict__ tw, const float* __restrict__ nw,
              float* __restrict__ out) {
    __shared__ float4 q_s[4][32];
    __shared__ float2 tg_s[4][32];

    int tid = threadIdx.x, lane = tid & 31, w = tid >> 5;
    int fg = blockIdx.x % FGRP;
    int b  = blockIdx.x / FGRP;
    int f0 = fg*4;
    int f  = min(f0 + w, NF-1);
    int beam = beam_id[b];

    float twr[8], twi[8], nwr[NNUL][8], nwi[NNUL][8];
    load_w_regs(tw, nw, beam, f, twr, twi, nwr, nwi);

    float pa = exp2f((float)(lane+1) * -1.5145732f);
    float carry[9];
    #pragma unroll
    for (int k = 0; k < 9; k++) carry[k] = 0.0f;

    for (int it = 0; it < 16; it++) {
        int t  = it*32 + lane;
        int tc = min(t, NT-1);
        float u[9], tr, ti;
        point_u(in, twr, twi, nwr, nwi, b, f, tc, u, tr, ti);
        scan9(u, lane);
        float y[9];
        #pragma unroll
        for (int k = 0; k < 9; k++) y[k] = fmaf(pa, carry[k], u[k]);
        #pragma unroll
        for (int k = 0; k < 9; k++) carry[k] = __shfl_sync(0xffffffffu, y[k], 31);

        // epilogue: q (with ratio), targ
        float rinv = __fdividef(1.0f, y[8] + 1e-13f);
        float q[4];
        #pragma unroll
        for (int n = 0; n < NNUL; n++) {
            float ph = sqrtf(fmaf(y[n], y[n], y[4+n]*y[4+n]));
            q[n] = fminf(fmaxf(ph*rinv, 0.01f), 1.0f);
        }
        if (t > 0 && t < NT) {
            float pinv = __fdividef(1.0f, g_pre[b*NT + t] + 1e-10f);
            float4 af = ((const float4*)g_aft)[b*NT + t];
            q[0] = sqrtf(q[0] * fminf(fmaxf(af.x*pinv, 0.01f), 1.0f));
            q[1] = sqrtf(q[1] * fminf(fmaxf(af.y*pinv, 0.01f), 1.0f));
            q[2] = sqrtf(q[2] * fminf(fmaxf(af.z*pinv, 0.01f), 1.0f));
            q[3] = sqrtf(q[3] * fminf(fmaxf(af.w*pinv, 0.01f), 1.0f));
        }
        q_s[w][lane]  = make_float4(q[0], q[1], q[2], q[3]);
        tg_s[w][lane] = make_float2(tr, ti);
        __syncthreads();

        // dcf store: thread = (t_local, fi); 64B contiguous runs per t
        {
            int tl = tid >> 2, fi = tid & 3;
            int tt = it*32 + tl;
            if (f0 + fi < NF && tt < NT)
                *(float4*)(out + ((size_t)(b*NT + tt)*NF + f0 + fi)*4) = q_s[fi][tl];
        }
        // targ store: thread = (p, t_local, fi-pair); 2 scalars each
        {
            int p = tid >> 6, rem = tid & 63, tl2 = rem >> 1, f2 = (rem & 1)*2;
            int tt2 = it*32 + tl2;
            if (tt2 < NT) {
                float2 v0 = tg_s[f2][tl2], v1 = tg_s[f2+1][tl2];
                float a0 = p ? v0.y : v0.x;
                float a1 = p ? v1.y : v1.x;
                size_t base = DCF_SIZE + ((size_t)(b*NT + tt2)*2 + p)*NF;
                if (f0 + f2   < NF) out[base + f0 + f2]   = a0;
                if (f0 + f2+1 < NF) out[base + f0 + f2+1] = a1;
            }
        }
        __syncthreads();
    }
}

// =================== launcher ===============================================
extern "C" void kernel_launch(void* const* d_in, const int* in_sizes, int n_in,
                              void* d_out, int out_size) {
    const float* in      = (const float*)d_in[0];
    const int*   beam_id = (const int*)  d_in[1];
    const float* tw      = (const float*)d_in[2];
    const float* nw      = (const float*)d_in[3];
    float* out = (float*)d_out;

    k0_zero<<<(NB*NT*NNUL + 255)/256, 256>>>();
    k2a_band<<<NB*BGRP, 128>>>(in, beam_id, tw, nw);
    k1_fused<<<NB*FGRP, 128>>>(in, beam_id, tw, nw, out);
}